// round 4
// baseline (speedup 1.0000x reference)
#include <cuda_runtime.h>
#include <cuda_bf16.h>

// Problem constants (fixed by setup_inputs)
#define NA   1024      // anchors
#define NB   8192      // database rows
#define DIM  128       // feature dim
#define KSEL 64        // top-K
#define BM   128       // rows (anchors) per block
#define BN   64        // cols (database) per block
#define KC   32        // K-chunk (4 chunks cover DIM=128)
#define PAD  34        // row stride in floats: 8B-aligned rows, conflict-free LDS.64

// Scratch (static device allocations are allowed)
__device__ float g_dist[2][NA][NB];     // 64 MB
__device__ int   g_neg[2][NA][KSEL];
__device__ float g_partial[NA];
__device__ unsigned g_done = 0;

// ---------- packed f32x2 helpers ----------
__device__ __forceinline__ unsigned long long f2add(unsigned long long a, unsigned long long b) {
    unsigned long long d;
    asm("add.rn.f32x2 %0, %1, %2;" : "=l"(d) : "l"(a), "l"(b));
    return d;
}
__device__ __forceinline__ unsigned long long f2abs(unsigned long long a) {
    return a & 0x7fffffff7fffffffULL;   // clear both sign bits (LOP3, alu pipe)
}

// ---------- pass 1: L1 cdist ----------
// side 0: A=out1 gathered by anchor1, B=out2.  side 1: A=out2 by anchor2, B=out1.
// 8(M)x4(N) outputs per thread, 256 threads -> 128x64 tile.
__global__ void __launch_bounds__(256, 2)
cdist_kernel(const float* __restrict__ out1, const float* __restrict__ out2,
             const int* __restrict__ a1, const int* __restrict__ a2)
{
    __shared__ float As[BM][PAD];   // 128*34*4 = 17408 B
    __shared__ float Bs[BN][PAD];   //  64*34*4 =  8704 B
    __shared__ int aidx[BM];

    const int side = blockIdx.z;
    const float* A = side ? out2 : out1;
    const float* B = side ? out1 : out2;
    const int* anch = side ? a2 : a1;

    const int tid = threadIdx.x;
    const int bm = blockIdx.y * BM;
    const int bn = blockIdx.x * BN;

    const int tx = tid & 15;   // N direction (4 cols, stride 16)
    const int ty = tid >> 4;   // M direction (8 rows, stride 16)

    if (tid < BM) aidx[tid] = __ldg(&anch[bm + tid]);
    __syncthreads();

    unsigned long long acc[8][4];
#pragma unroll
    for (int m = 0; m < 8; m++)
#pragma unroll
        for (int n = 0; n < 4; n++) acc[m][n] = 0ULL;

    for (int kc = 0; kc < DIM; kc += KC) {
        // A chunk: 128 rows x 16 float2
        for (int u = tid; u < BM * 16; u += 256) {
            int r = u >> 4, kq = u & 15;
            float2 v = *(const float2*)&A[(long long)aidx[r] * DIM + kc + kq * 2];
            *(float2*)&As[r][kq * 2] = v;
        }
        // B chunk: 64 rows x 16 float2, negated
        for (int u = tid; u < BN * 16; u += 256) {
            int r = u >> 4, kq = u & 15;
            float2 v = *(const float2*)&B[(long long)(bn + r) * DIM + kc + kq * 2];
            v.x = -v.x; v.y = -v.y;
            *(float2*)&Bs[r][kq * 2] = v;
        }
        __syncthreads();

#pragma unroll 2
        for (int kk = 0; kk < KC; kk += 2) {
            unsigned long long av[8], bv[4];
#pragma unroll
            for (int m = 0; m < 8; m++) av[m] = *(const unsigned long long*)&As[ty + 16 * m][kk];
#pragma unroll
            for (int n = 0; n < 4; n++) bv[n] = *(const unsigned long long*)&Bs[tx + 16 * n][kk];
#pragma unroll
            for (int m = 0; m < 8; m++)
#pragma unroll
                for (int n = 0; n < 4; n++)
                    acc[m][n] = f2add(acc[m][n], f2abs(f2add(av[m], bv[n])));
        }
        __syncthreads();
    }

    float* dbase = &g_dist[side][0][0];
#pragma unroll
    for (int m = 0; m < 8; m++)
#pragma unroll
        for (int n = 0; n < 4; n++) {
            unsigned long long v = acc[m][n];
            float lo = __uint_as_float((unsigned)v);
            float hi = __uint_as_float((unsigned)(v >> 32));
            dbase[(long long)(bm + ty + 16 * m) * NB + (bn + tx + 16 * n)] = lo + hi;
        }
}

// ---------- pass 2: exact top-64 via 4x8-bit radix select (row staged in smem) ----------
__global__ void __launch_bounds__(256) topk_kernel()
{
    const int row  = blockIdx.x;
    const int side = blockIdx.y;
    const uint4* __restrict__ urow4 = (const uint4*)g_dist[side][row];

    __shared__ unsigned sv[NB];        // 32 KB: one full row
    __shared__ int hist[256];
    __shared__ int s_bucket, s_cum;
    __shared__ int c_less, c_eq;
    __shared__ int eqi[64];

    const int tid  = threadIdx.x;
    const int lane = tid & 31;

    // Stage the row: one pass over HBM/L2
#pragma unroll
    for (int u = tid; u < NB / 4; u += 256)
        *(uint4*)&sv[u * 4] = urow4[u];
    __syncthreads();

    unsigned prefix = 0;
    int remaining = KSEL;

    for (int pass = 0; pass < 4; pass++) {
        const int shift = 24 - 8 * pass;
        hist[tid] = 0;
        __syncthreads();
        for (int j = tid; j < NB; j += 256) {
            unsigned v = sv[j];
            bool ok = (pass == 0) || ((v >> (shift + 8)) == prefix);
            unsigned mask = __ballot_sync(0xffffffffu, ok);
            if (ok) {
                int b = (v >> shift) & 255;
                unsigned mm = __match_any_sync(mask, b);
                int leader = __ffs(mm) - 1;
                if (lane == leader) atomicAdd(&hist[b], __popc(mm));
            }
        }
        __syncthreads();
        if (tid == 0) {
            int cum = 0, b = 0;
            for (; b < 255; b++) {
                if (cum + hist[b] >= remaining) break;
                cum += hist[b];
            }
            s_bucket = b; s_cum = cum;
        }
        __syncthreads();
        remaining -= s_cum;
        prefix = (prefix << 8) | (unsigned)s_bucket;
    }

    const unsigned T = prefix;      // bit pattern of the 64th-smallest value
    const int need  = remaining;    // how many equal-to-T entries we take

    if (tid == 0) { c_less = 0; c_eq = 0; }
    __syncthreads();

    int* outp = g_neg[side][row];
    for (int j = tid; j < NB; j += 256) {
        unsigned v = sv[j];
        if (v < T) {
            outp[atomicAdd(&c_less, 1)] = j;
        } else if (v == T) {
            int p = atomicAdd(&c_eq, 1);
            if (p < 64) eqi[p] = j;
        }
    }
    __syncthreads();
    if (tid == 0) {
        int ne = c_eq < 64 ? c_eq : 64;
        int base = c_less;
        for (int s = 0; s < need; s++) {          // smallest indices first (stable argsort tie rule)
            int best = 0x7fffffff, bi = 0;
            for (int t = 0; t < ne; t++)
                if (eqi[t] < best) { best = eqi[t]; bi = t; }
            outp[base + s] = best;
            eqi[bi] = 0x7fffffff;
        }
    }
}

// ---------- pass 3: weighted ranking loss per anchor + fused final reduction ----------
__global__ void loss_kernel(const float* __restrict__ out1, const float* __restrict__ out2,
                            const float* __restrict__ ot,
                            const int* __restrict__ a1i, const int* __restrict__ a2i,
                            float* __restrict__ outp)
{
    const int i = blockIdx.x;
    const int tid = threadIdx.x, lane = tid & 31, w = tid >> 5;

    __shared__ float a1s[DIM], a2s[DIM];
    __shared__ float red[8];
    __shared__ float Dm_s;
    __shared__ bool isLast;

    const int ia1 = a1i[i], ia2 = a2i[i];
    if (tid < DIM) {
        a1s[tid] = out1[(long long)ia1 * DIM + tid];
        a2s[tid] = out2[(long long)ia2 * DIM + tid];
    }
    __syncthreads();

    float p = (tid < DIM) ? fabsf(a1s[tid] - a2s[tid]) : 0.0f;
#pragma unroll
    for (int o = 16; o; o >>= 1) p += __shfl_xor_sync(0xffffffffu, p, o);
    if (lane == 0) red[w] = p;
    __syncthreads();
    if (tid == 0) {
        float s = 0.0f;
        for (int k = 0; k < 8; k++) s += red[k];
        Dm_s = s + 1.0f;  // MARGIN
    }
    __syncthreads();
    const float Dm = Dm_s;

    float wsum = 0.0f;
    for (int t = w; t < 2 * KSEL; t += 8) {
        const int side = t >> 6, s = t & 63;
        const int j = g_neg[side][i][s];
        float sm = 0.0f;
        if (side == 0) {
            float wgt = ot[(long long)ia1 * NB + j];
            for (int d = lane; d < DIM; d += 32)
                sm += fabsf(a1s[d] - wgt * out2[(long long)j * DIM + d]);
        } else {
            float wgt = ot[(long long)j * NB + ia2];
            for (int d = lane; d < DIM; d += 32)
                sm += fabsf(a2s[d] - wgt * out1[(long long)j * DIM + d]);
        }
#pragma unroll
        for (int o = 16; o; o >>= 1) sm += __shfl_xor_sync(0xffffffffu, sm, o);
        if (lane == 0) wsum += fmaxf(Dm - sm, 0.0f);
    }
    if (lane == 0) red[w] = wsum;
    __syncthreads();
    if (tid == 0) {
        float s = 0.0f;
        for (int k = 0; k < 8; k++) s += red[k];
        g_partial[i] = s;
        __threadfence();
        unsigned v = atomicAdd(&g_done, 1u);
        isLast = (v == NA - 1);
    }
    __syncthreads();

    // Last block performs the deterministic final reduction
    if (isLast) {
        __shared__ float sh[256];
        float s = 0.0f;
        for (int k = tid; k < NA; k += 256) s += g_partial[k];
        sh[tid] = s;
        __syncthreads();
        for (int o = 128; o; o >>= 1) {
            if (tid < o) sh[tid] += sh[tid + o];
            __syncthreads();
        }
        if (tid == 0) {
            outp[0] = sh[0] * (1.0f / ((float)NA * (float)KSEL));
            g_done = 0;   // reset for next graph replay
        }
    }
}

extern "C" void kernel_launch(void* const* d_in, const int* in_sizes, int n_in,
                              void* d_out, int out_size)
{
    const float* out1 = (const float*)d_in[0];
    const float* out2 = (const float*)d_in[1];
    const float* ot   = (const float*)d_in[2];
    const int*   a1   = (const int*)d_in[3];
    const int*   a2   = (const int*)d_in[4];
    float* outp = (float*)d_out;

    dim3 cgrid(NB / BN, NA / BM, 2);
    cdist_kernel<<<cgrid, 256>>>(out1, out2, a1, a2);
    topk_kernel<<<dim3(NA, 2), 256>>>();
    loss_kernel<<<NA, 256>>>(out1, out2, ot, a1, a2, outp);
}